// round 1
// baseline (speedup 1.0000x reference)
#include <cuda_runtime.h>
#include <math.h>

// ---------------------------------------------------------------------------
// YOLOv1 loss, fused single-pass streaming reduction.
// pred:   [B,14,14,90] f32   target: [B,14,14,90] f32   out: scalar f32
//
// acc layout:
//  0 coord  (sum m1*(xy1+wh1)+m2*(xy2+wh2))        -> * LAMBDA_COORD
//  1 conf   (sum m1*((pc1-iou1)^2+pc2^2)+m2*(...))
//  2 noobjA (sum noobj*pc1^2)
//  3 n_noobj
//  4 sum pc2^2 over ALL cells
//  5 n1
//  6 n2
//  7 cls1 (sum m1 * sum_c (pcls-tcls)^2)
//  8 cls2
// ---------------------------------------------------------------------------

#define SGRID 14
#define NCLS  80
#define STRIDE 90
#define LAMBDA_COORD 5.0f
#define LAMBDA_NOOBJ 0.5f
#define EPS_IOU 1e-6f
#define EPS_WH  1e-8f

__device__ float        g_acc[9];
__device__ unsigned int g_nan;

__global__ void yolo_zero_kernel() {
    if (threadIdx.x < 9)  g_acc[threadIdx.x] = 0.0f;
    if (threadIdx.x == 9) g_nan = 0u;
}

__device__ __forceinline__ float iou_img(float x1, float y1, float w1, float h1,
                                         float x2, float y2, float w2, float h2) {
    float ix0 = fmaxf(x1 - w1 * 0.5f, x2 - w2 * 0.5f);
    float iy0 = fmaxf(y1 - h1 * 0.5f, y2 - h2 * 0.5f);
    float ix1 = fminf(x1 + w1 * 0.5f, x2 + w2 * 0.5f);
    float iy1 = fminf(y1 + h1 * 0.5f, y2 + h2 * 0.5f);
    float inter = fmaxf(ix1 - ix0, 0.0f) * fmaxf(iy1 - iy0, 0.0f);
    float uni   = w1 * h1 + w2 * h2 - inter;
    return inter / (uni + EPS_IOU);
}

__global__ void __launch_bounds__(256)
yolo_main_kernel(const float* __restrict__ pred,
                 const float* __restrict__ targ,
                 int ncells)
{
    const unsigned FULL = 0xffffffffu;
    const int lane = threadIdx.x & 31;
    const int wib  = threadIdx.x >> 5;          // warp in block (0..7)
    const int nwb  = blockDim.x >> 5;           // 8
    const int gw   = blockIdx.x * nwb + wib;    // global warp id
    const int nw   = gridDim.x * nwb;           // total warps

    float a[9];
#pragma unroll
    for (int i = 0; i < 9; i++) a[i] = 0.0f;
    unsigned int nanf = 0u;

    for (int c = gw; c < ncells; c += nw) {
        const float* p = pred + (size_t)c * STRIDE;
        const float* t = targ + (size_t)c * STRIDE;

        // Three coalesced passes cover elements [0,32), [32,64), [64,90).
        float p0 = p[lane];
        float t0 = t[lane];
        float p1 = p[32 + lane];
        float t1 = t[32 + lane];
        float p2 = 0.0f, t2 = 0.0f;
        if (lane < 26) { p2 = p[64 + lane]; t2 = t[64 + lane]; }

        nanf |= (p0 != p0) | (p1 != p1) | (p2 != p2)
              | (t0 != t0) | (t1 != t1) | (t2 != t2);

        // per-lane class SSE contribution (elements 10..89)
        float cls = 0.0f, d;
        if (lane >= 10) { d = p0 - t0; cls += d * d; }
        d = p1 - t1; cls += d * d;
        if (lane < 26) { d = p2 - t2; cls += d * d; }

        // gather the 15 scalar values (all from pass 0) to every lane
        float px1 = __shfl_sync(FULL, p0, 0);
        float py1 = __shfl_sync(FULL, p0, 1);
        float pw1 = __shfl_sync(FULL, p0, 2);
        float ph1 = __shfl_sync(FULL, p0, 3);
        float pc1 = __shfl_sync(FULL, p0, 4);
        float px2 = __shfl_sync(FULL, p0, 5);
        float py2 = __shfl_sync(FULL, p0, 6);
        float pw2 = __shfl_sync(FULL, p0, 7);
        float ph2 = __shfl_sync(FULL, p0, 8);
        float pc2 = __shfl_sync(FULL, p0, 9);
        float tx  = __shfl_sync(FULL, t0, 0);
        float ty  = __shfl_sync(FULL, t0, 1);
        float tw  = __shfl_sync(FULL, t0, 2);
        float th  = __shfl_sync(FULL, t0, 3);
        float tcf = __shfl_sync(FULL, t0, 4);

        // cell coordinates: c = (b*S + i)*S + j ; cell_y = i, cell_x = j
        float cx = (float)(c % SGRID);
        float cy = (float)((c / SGRID) % SGRID);

        float X1 = (cx + px1) / (float)SGRID, Y1 = (cy + py1) / (float)SGRID;
        float X2 = (cx + px2) / (float)SGRID, Y2 = (cy + py2) / (float)SGRID;
        float TX = (cx + tx ) / (float)SGRID, TY = (cy + ty ) / (float)SGRID;

        float iou1 = iou_img(X1, Y1, pw1, ph1, TX, TY, tw, th);
        float iou2 = iou_img(X2, Y2, pw2, ph2, TX, TY, tw, th);

        bool obj   = (tcf == 1.0f);
        bool noobj = (tcf == 0.0f);
        float m1 = (obj && (iou1 >= iou2)) ? 1.0f : 0.0f;
        float m2 = (obj && (iou1 <  iou2)) ? 1.0f : 0.0f;

        // class loss: every lane adds its own portion (m1/m2 identical on all lanes)
        a[7] += m1 * cls;
        a[8] += m2 * cls;

        if (lane == 0) {
            a[4] += pc2 * pc2;                  // over ALL cells (noobj2 numerator)
            if (noobj) {
                a[2] += pc1 * pc1;
                a[3] += 1.0f;
            }
            if (obj) {
                float sw1 = sqrtf(fmaxf(pw1, EPS_WH)) - sqrtf(fmaxf(tw, EPS_WH));
                float sh1 = sqrtf(fmaxf(ph1, EPS_WH)) - sqrtf(fmaxf(th, EPS_WH));
                float sw2 = sqrtf(fmaxf(pw2, EPS_WH)) - sqrtf(fmaxf(tw, EPS_WH));
                float sh2 = sqrtf(fmaxf(ph2, EPS_WH)) - sqrtf(fmaxf(th, EPS_WH));
                float c1 = (px1 - tx) * (px1 - tx) + (py1 - ty) * (py1 - ty)
                         + sw1 * sw1 + sh1 * sh1;
                float c2 = (px2 - tx) * (px2 - tx) + (py2 - ty) * (py2 - ty)
                         + sw2 * sw2 + sh2 * sh2;
                a[0] += m1 * c1 + m2 * c2;
                float e1 = pc1 - iou1;
                float e2 = pc2 - iou2;
                a[1] += m1 * (e1 * e1 + pc2 * pc2) + m2 * (e2 * e2 + pc1 * pc1);
                a[5] += m1;
                a[6] += m2;
            }
        }
    }

    // ---- warp reduction ----
#pragma unroll
    for (int i = 0; i < 9; i++) {
        float v = a[i];
#pragma unroll
        for (int o = 16; o > 0; o >>= 1) v += __shfl_down_sync(FULL, v, o);
        a[i] = v;
    }
    unsigned int nanw = __any_sync(FULL, nanf != 0u) ? 1u : 0u;

    // ---- block reduction (blockDim == 256 -> 8 warps) ----
    __shared__ float        sb[8][9];
    __shared__ unsigned int sn[8];
    if (lane == 0) {
#pragma unroll
        for (int i = 0; i < 9; i++) sb[wib][i] = a[i];
        sn[wib] = nanw;
    }
    __syncthreads();
    if (threadIdx.x < 9) {
        float v = 0.0f;
        for (int w = 0; w < nwb; w++) v += sb[w][threadIdx.x];
        atomicAdd(&g_acc[threadIdx.x], v);
    }
    if (threadIdx.x == 9) {
        unsigned int v = 0u;
        for (int w = 0; w < nwb; w++) v |= sn[w];
        if (v) atomicOr(&g_nan, 1u);
    }
}

__global__ void yolo_finalize_kernel(float* __restrict__ out, int ncells) {
    float coord   = LAMBDA_COORD * g_acc[0];
    float conf    = g_acc[1];
    float n_noobj = g_acc[3];
    float noobj1  = g_acc[2] / fmaxf(n_noobj, 1.0f);
    float noobj2  = g_acc[4] / (float)ncells;           // mean over all cells
    if (n_noobj > 0.0f) conf += LAMBDA_NOOBJ * (noobj1 + noobj2);
    float n1 = g_acc[5], n2 = g_acc[6];
    float cls_loss = 0.0f;
    if (n1 > 0.0f) cls_loss += g_acc[7] / fmaxf(n1 * (float)NCLS, 1.0f);
    if (n2 > 0.0f) cls_loss += g_acc[8] / fmaxf(n2 * (float)NCLS, 1.0f);
    float B = (float)ncells / (float)(SGRID * SGRID);
    float total = (coord + conf + cls_loss) / B;
    out[0] = g_nan ? 0.0f : total;
}

extern "C" void kernel_launch(void* const* d_in, const int* in_sizes, int n_in,
                              void* d_out, int out_size) {
    const float* pred = (const float*)d_in[0];
    const float* targ = (const float*)d_in[1];
    float* out = (float*)d_out;

    int total_elems = in_sizes[0];          // B * 14 * 14 * 90
    int ncells = total_elems / STRIDE;      // B * 196

    yolo_zero_kernel<<<1, 32>>>();
    yolo_main_kernel<<<1480, 256>>>(pred, targ, ncells);
    yolo_finalize_kernel<<<1, 1>>>(out, ncells);
}

// round 2
// speedup vs baseline: 2.2179x; 2.2179x over previous
#include <cuda_runtime.h>
#include <math.h>

// ---------------------------------------------------------------------------
// YOLOv1 loss — block-per-group staged streaming reduction.
// pred/target: [B,14,14,90] f32, out: scalar f32.
//
// Each block iterates over groups of 64 cells:
//   A) stage 64*90 floats of pred+target into smem via float4 (NaN-checked)
//   B) 64 threads compute per-cell scalar terms (IoU, coord, conf, counts),
//      emit compacted list of responsible cells
//   C) all 256 threads compute class SSE only for responsible cells (~5%)
// Per-thread accumulators -> one block reduce -> 9 atomics per block.
//
// g_acc: 0 coord  1 conf  2 noobj1_num  3 n_noobj  4 sum(pc2^2)
//        5 n1     6 n2    7 cls1        8 cls2     9 nan flag
// ---------------------------------------------------------------------------

#define SGRID  14
#define NCLS   80
#define STRIDE 90
#define CELLS  64                       // cells per group (even => 16B-aligned base)
#define GROUP_F (CELLS * STRIDE)        // 5760 floats
#define LAMBDA_COORD 5.0f
#define LAMBDA_NOOBJ 0.5f
#define EPS_IOU 1e-6f
#define EPS_WH  1e-8f

__device__ float g_acc[10];

__global__ void yolo_zero_kernel() {
    if (threadIdx.x < 10) g_acc[threadIdx.x] = 0.0f;
}

__device__ __forceinline__ float iou_img(float x1, float y1, float w1, float h1,
                                         float x2, float y2, float w2, float h2) {
    float ix0 = fmaxf(x1 - w1 * 0.5f, x2 - w2 * 0.5f);
    float iy0 = fmaxf(y1 - h1 * 0.5f, y2 - h2 * 0.5f);
    float ix1 = fminf(x1 + w1 * 0.5f, x2 + w2 * 0.5f);
    float iy1 = fminf(y1 + h1 * 0.5f, y2 + h2 * 0.5f);
    float inter = fmaxf(ix1 - ix0, 0.0f) * fmaxf(iy1 - iy0, 0.0f);
    float uni   = w1 * h1 + w2 * h2 - inter;
    return inter / (uni + EPS_IOU);
}

__global__ void __launch_bounds__(256, 4)
yolo_main_kernel(const float* __restrict__ pred,
                 const float* __restrict__ targ,
                 int ncells)
{
    __shared__ float sp[GROUP_F];
    __shared__ float st[GROUP_F];
    __shared__ float sm_m[CELLS];       // +1 resp1, -1 resp2, 0 none
    __shared__ int   s_list[CELLS];
    __shared__ int   s_cnt;
    __shared__ float sb[8][9];
    __shared__ unsigned int sn[8];

    const unsigned FULL = 0xffffffffu;
    const int tid  = threadIdx.x;
    const int lane = tid & 31;
    const int wib  = tid >> 5;
    const int ngroups = (ncells + CELLS - 1) / CELLS;

    float a[9];
#pragma unroll
    for (int i = 0; i < 9; i++) a[i] = 0.0f;
    unsigned int nanf = 0u;

    for (int g = blockIdx.x; g < ngroups; g += gridDim.x) {
        const int cbase = g * CELLS;
        const int cells = min(CELLS, ncells - cbase);
        const int nf    = cells * STRIDE;
        const int nv    = nf >> 2;

        // ---- Phase A: stage group into smem (float4, NaN-checked) ----
        const float4* pg = (const float4*)(pred + (size_t)cbase * STRIDE);
        const float4* tg = (const float4*)(targ + (size_t)cbase * STRIDE);
        if (tid == 0) s_cnt = 0;
#pragma unroll
        for (int k = 0; k < 6; k++) {
            int i2 = tid + k * 256;
            if (i2 < nv) {
                float4 v = pg[i2];
                float4 w = tg[i2];
                ((float4*)sp)[i2] = v;
                ((float4*)st)[i2] = w;
                nanf |= (unsigned)((v.x != v.x) | (v.y != v.y) |
                                   (v.z != v.z) | (v.w != v.w) |
                                   (w.x != w.x) | (w.y != w.y) |
                                   (w.z != w.z) | (w.w != w.w));
            }
        }
        // scalar tail (nf not multiple of 4 only possible on odd tails)
        if (tid < (nf & 3)) {
            int i3 = nv * 4 + tid;
            float v = (pred + (size_t)cbase * STRIDE)[i3];
            float w = (targ + (size_t)cbase * STRIDE)[i3];
            sp[i3] = v; st[i3] = w;
            nanf |= (unsigned)((v != v) | (w != w));
        }
        __syncthreads();

        // ---- Phase B: per-cell scalars (one thread per cell) ----
        if (tid < cells) {
            const int base = tid * STRIDE;
            float px1 = sp[base + 0], py1 = sp[base + 1];
            float pw1 = sp[base + 2], ph1 = sp[base + 3];
            float pc1 = sp[base + 4];
            float px2 = sp[base + 5], py2 = sp[base + 6];
            float pw2 = sp[base + 7], ph2 = sp[base + 8];
            float pc2 = sp[base + 9];
            float tx  = st[base + 0], ty = st[base + 1];
            float tw  = st[base + 2], th = st[base + 3];
            float tcf = st[base + 4];

            int gc = cbase + tid;
            float cx = (float)(gc % SGRID);
            float cy = (float)((gc / SGRID) % SGRID);

            const float invS = 1.0f / (float)SGRID;
            float X1 = (cx + px1) * invS, Y1 = (cy + py1) * invS;
            float X2 = (cx + px2) * invS, Y2 = (cy + py2) * invS;
            float TX = (cx + tx ) * invS, TY = (cy + ty ) * invS;

            float iou1 = iou_img(X1, Y1, pw1, ph1, TX, TY, tw, th);
            float iou2 = iou_img(X2, Y2, pw2, ph2, TX, TY, tw, th);

            bool obj   = (tcf == 1.0f);
            bool noobj = (tcf == 0.0f);

            a[4] += pc2 * pc2;                       // all cells
            if (noobj) { a[2] += pc1 * pc1; a[3] += 1.0f; }

            float m = 0.0f;
            if (obj) {
                bool r1 = (iou1 >= iou2);
                m = r1 ? 1.0f : -1.0f;
                float sw1 = sqrtf(fmaxf(pw1, EPS_WH)) - sqrtf(fmaxf(tw, EPS_WH));
                float sh1 = sqrtf(fmaxf(ph1, EPS_WH)) - sqrtf(fmaxf(th, EPS_WH));
                float sw2 = sqrtf(fmaxf(pw2, EPS_WH)) - sqrtf(fmaxf(tw, EPS_WH));
                float sh2 = sqrtf(fmaxf(ph2, EPS_WH)) - sqrtf(fmaxf(th, EPS_WH));
                float c1 = (px1 - tx) * (px1 - tx) + (py1 - ty) * (py1 - ty)
                         + sw1 * sw1 + sh1 * sh1;
                float c2 = (px2 - tx) * (px2 - tx) + (py2 - ty) * (py2 - ty)
                         + sw2 * sw2 + sh2 * sh2;
                float e1 = pc1 - iou1;
                float e2 = pc2 - iou2;
                if (r1) {
                    a[0] += c1;
                    a[1] += e1 * e1 + pc2 * pc2;
                    a[5] += 1.0f;
                } else {
                    a[0] += c2;
                    a[1] += e2 * e2 + pc1 * pc1;
                    a[6] += 1.0f;
                }
                int pos = atomicAdd(&s_cnt, 1);
                s_list[pos] = tid;
            }
            sm_m[tid] = m;
        }
        __syncthreads();

        // ---- Phase C: class SSE, responsible cells only ----
        const int tot = s_cnt * NCLS;
        for (int e = tid; e < tot; e += 256) {
            int k = e / NCLS;
            int j = e - k * NCLS;
            int i = s_list[k];
            int off = i * STRIDE + 10 + j;
            float d = sp[off] - st[off];
            float dd = d * d;
            if (sm_m[i] > 0.0f) a[7] += dd; else a[8] += dd;
        }
        __syncthreads();   // protect smem before next group's staging
    }

    // ---- warp reduction ----
#pragma unroll
    for (int i = 0; i < 9; i++) {
        float v = a[i];
#pragma unroll
        for (int o = 16; o > 0; o >>= 1) v += __shfl_down_sync(FULL, v, o);
        a[i] = v;
    }
    unsigned int nanw = __any_sync(FULL, nanf != 0u) ? 1u : 0u;

    // ---- block reduction -> atomics ----
    if (lane == 0) {
#pragma unroll
        for (int i = 0; i < 9; i++) sb[wib][i] = a[i];
        sn[wib] = nanw;
    }
    __syncthreads();
    if (tid < 9) {
        float v = 0.0f;
#pragma unroll
        for (int w = 0; w < 8; w++) v += sb[w][tid];
        atomicAdd(&g_acc[tid], v);
    }
    if (tid == 9) {
        unsigned int v = 0u;
#pragma unroll
        for (int w = 0; w < 8; w++) v |= sn[w];
        if (v) atomicAdd(&g_acc[9], 1.0f);
    }
}

__global__ void yolo_finalize_kernel(float* __restrict__ out, int ncells) {
    float coord   = LAMBDA_COORD * g_acc[0];
    float conf    = g_acc[1];
    float n_noobj = g_acc[3];
    float noobj1  = g_acc[2] / fmaxf(n_noobj, 1.0f);
    float noobj2  = g_acc[4] / (float)ncells;
    if (n_noobj > 0.0f) conf += LAMBDA_NOOBJ * (noobj1 + noobj2);
    float n1 = g_acc[5], n2 = g_acc[6];
    float cls_loss = 0.0f;
    if (n1 > 0.0f) cls_loss += g_acc[7] / fmaxf(n1 * (float)NCLS, 1.0f);
    if (n2 > 0.0f) cls_loss += g_acc[8] / fmaxf(n2 * (float)NCLS, 1.0f);
    float B = (float)ncells / (float)(SGRID * SGRID);
    float total = (coord + conf + cls_loss) / B;
    out[0] = (g_acc[9] != 0.0f) ? 0.0f : total;
}

extern "C" void kernel_launch(void* const* d_in, const int* in_sizes, int n_in,
                              void* d_out, int out_size) {
    const float* pred = (const float*)d_in[0];
    const float* targ = (const float*)d_in[1];
    float* out = (float*)d_out;

    int total_elems = in_sizes[0];
    int ncells = total_elems / STRIDE;

    yolo_zero_kernel<<<1, 32>>>();
    yolo_main_kernel<<<608, 256>>>(pred, targ, ncells);   // 152 SMs * 4 blocks
    yolo_finalize_kernel<<<1, 1>>>(out, ncells);
}

// round 3
// speedup vs baseline: 2.3057x; 1.0396x over previous
#include <cuda_runtime.h>
#include <math.h>

// ---------------------------------------------------------------------------
// YOLOv1 loss — single fused kernel (staging + reduction + finalize).
// pred/target: [B,14,14,90] f32, out: scalar f32.
//
// Each block iterates over groups of 64 cells:
//   A) stage 64*90 floats of pred+target into smem via float4 (NaN-checked)
//   B) 64 threads compute per-cell scalar terms, compact responsible cells
//   C) 256 threads compute class SSE only for responsible cells (~5%)
// Block reduce -> 9-10 global atomics -> last-block finalize writes scalar
// and resets global state (deterministic across graph replays).
//
// g_acc: 0 coord  1 conf  2 noobj1_num  3 n_noobj  4 sum(pc2^2)
//        5 n1     6 n2    7 cls1        8 cls2     9 nan flag
// ---------------------------------------------------------------------------

#define SGRID  14
#define NCLS   80
#define STRIDE 90
#define CELLS  64
#define GROUP_F (CELLS * STRIDE)        // 5760 floats
#define NBLOCKS 608
#define LAMBDA_COORD 5.0f
#define LAMBDA_NOOBJ 0.5f
#define EPS_IOU 1e-6f
#define EPS_WH  1e-8f

__device__ float        g_acc[10] = {0};
__device__ unsigned int g_count   = 0;

__device__ __forceinline__ float iou_img(float x1, float y1, float w1, float h1,
                                         float x2, float y2, float w2, float h2) {
    float ix0 = fmaxf(x1 - w1 * 0.5f, x2 - w2 * 0.5f);
    float iy0 = fmaxf(y1 - h1 * 0.5f, y2 - h2 * 0.5f);
    float ix1 = fminf(x1 + w1 * 0.5f, x2 + w2 * 0.5f);
    float iy1 = fminf(y1 + h1 * 0.5f, y2 + h2 * 0.5f);
    float inter = fmaxf(ix1 - ix0, 0.0f) * fmaxf(iy1 - iy0, 0.0f);
    float uni   = w1 * h1 + w2 * h2 - inter;
    return inter / (uni + EPS_IOU);
}

__global__ void __launch_bounds__(256, 4)
yolo_fused_kernel(const float* __restrict__ pred,
                  const float* __restrict__ targ,
                  float* __restrict__ out,
                  int ncells)
{
    __shared__ float sp[GROUP_F];
    __shared__ float st[GROUP_F];
    __shared__ float sm_m[CELLS];       // +1 resp1, -1 resp2, 0 none
    __shared__ int   s_list[CELLS];
    __shared__ int   s_cnt;
    __shared__ float sb[8][9];
    __shared__ unsigned int sn[8];
    __shared__ bool  is_last;

    const unsigned FULL = 0xffffffffu;
    const int tid  = threadIdx.x;
    const int lane = tid & 31;
    const int wib  = tid >> 5;
    const int ngroups = (ncells + CELLS - 1) / CELLS;

    float a[9];
#pragma unroll
    for (int i = 0; i < 9; i++) a[i] = 0.0f;
    unsigned int nanf = 0u;

    for (int g = blockIdx.x; g < ngroups; g += gridDim.x) {
        const int cbase = g * CELLS;
        const int cells = min(CELLS, ncells - cbase);
        const int nf    = cells * STRIDE;
        const int nv    = nf >> 2;

        // ---- Phase A: stage group into smem (float4, NaN-checked) ----
        const float4* pg = (const float4*)(pred + (size_t)cbase * STRIDE);
        const float4* tg = (const float4*)(targ + (size_t)cbase * STRIDE);
        if (tid == 0) s_cnt = 0;
#pragma unroll
        for (int k = 0; k < 6; k++) {
            int i2 = tid + k * 256;
            if (i2 < nv) {
                float4 v = pg[i2];
                float4 w = tg[i2];
                ((float4*)sp)[i2] = v;
                ((float4*)st)[i2] = w;
                nanf |= (unsigned)((v.x != v.x) | (v.y != v.y) |
                                   (v.z != v.z) | (v.w != v.w) |
                                   (w.x != w.x) | (w.y != w.y) |
                                   (w.z != w.z) | (w.w != w.w));
            }
        }
        if (tid < (nf & 3)) {
            int i3 = nv * 4 + tid;
            float v = (pred + (size_t)cbase * STRIDE)[i3];
            float w = (targ + (size_t)cbase * STRIDE)[i3];
            sp[i3] = v; st[i3] = w;
            nanf |= (unsigned)((v != v) | (w != w));
        }
        __syncthreads();

        // ---- Phase B: per-cell scalars (one thread per cell) ----
        if (tid < cells) {
            const int base = tid * STRIDE;
            float px1 = sp[base + 0], py1 = sp[base + 1];
            float pw1 = sp[base + 2], ph1 = sp[base + 3];
            float pc1 = sp[base + 4];
            float px2 = sp[base + 5], py2 = sp[base + 6];
            float pw2 = sp[base + 7], ph2 = sp[base + 8];
            float pc2 = sp[base + 9];
            float tx  = st[base + 0], ty = st[base + 1];
            float tw  = st[base + 2], th = st[base + 3];
            float tcf = st[base + 4];

            int gc = cbase + tid;
            float cx = (float)(gc % SGRID);
            float cy = (float)((gc / SGRID) % SGRID);

            const float invS = 1.0f / (float)SGRID;
            float X1 = (cx + px1) * invS, Y1 = (cy + py1) * invS;
            float X2 = (cx + px2) * invS, Y2 = (cy + py2) * invS;
            float TX = (cx + tx ) * invS, TY = (cy + ty ) * invS;

            float iou1 = iou_img(X1, Y1, pw1, ph1, TX, TY, tw, th);
            float iou2 = iou_img(X2, Y2, pw2, ph2, TX, TY, tw, th);

            bool obj   = (tcf == 1.0f);
            bool noobj = (tcf == 0.0f);

            a[4] += pc2 * pc2;
            if (noobj) { a[2] += pc1 * pc1; a[3] += 1.0f; }

            float m = 0.0f;
            if (obj) {
                bool r1 = (iou1 >= iou2);
                m = r1 ? 1.0f : -1.0f;
                float sw1 = sqrtf(fmaxf(pw1, EPS_WH)) - sqrtf(fmaxf(tw, EPS_WH));
                float sh1 = sqrtf(fmaxf(ph1, EPS_WH)) - sqrtf(fmaxf(th, EPS_WH));
                float sw2 = sqrtf(fmaxf(pw2, EPS_WH)) - sqrtf(fmaxf(tw, EPS_WH));
                float sh2 = sqrtf(fmaxf(ph2, EPS_WH)) - sqrtf(fmaxf(th, EPS_WH));
                float c1 = (px1 - tx) * (px1 - tx) + (py1 - ty) * (py1 - ty)
                         + sw1 * sw1 + sh1 * sh1;
                float c2 = (px2 - tx) * (px2 - tx) + (py2 - ty) * (py2 - ty)
                         + sw2 * sw2 + sh2 * sh2;
                float e1 = pc1 - iou1;
                float e2 = pc2 - iou2;
                if (r1) {
                    a[0] += c1;
                    a[1] += e1 * e1 + pc2 * pc2;
                    a[5] += 1.0f;
                } else {
                    a[0] += c2;
                    a[1] += e2 * e2 + pc1 * pc1;
                    a[6] += 1.0f;
                }
                int pos = atomicAdd(&s_cnt, 1);
                s_list[pos] = tid;
            }
            sm_m[tid] = m;
        }
        __syncthreads();

        // ---- Phase C: class SSE, responsible cells only ----
        const int tot = s_cnt * NCLS;
        for (int e = tid; e < tot; e += 256) {
            int k = e / NCLS;
            int j = e - k * NCLS;
            int i = s_list[k];
            int off = i * STRIDE + 10 + j;
            float d = sp[off] - st[off];
            float dd = d * d;
            if (sm_m[i] > 0.0f) a[7] += dd; else a[8] += dd;
        }
        __syncthreads();
    }

    // ---- warp reduction ----
#pragma unroll
    for (int i = 0; i < 9; i++) {
        float v = a[i];
#pragma unroll
        for (int o = 16; o > 0; o >>= 1) v += __shfl_down_sync(FULL, v, o);
        a[i] = v;
    }
    unsigned int nanw = __any_sync(FULL, nanf != 0u) ? 1u : 0u;

    // ---- block reduction -> global atomics ----
    if (lane == 0) {
#pragma unroll
        for (int i = 0; i < 9; i++) sb[wib][i] = a[i];
        sn[wib] = nanw;
    }
    __syncthreads();
    if (tid < 9) {
        float v = 0.0f;
#pragma unroll
        for (int w = 0; w < 8; w++) v += sb[w][tid];
        atomicAdd(&g_acc[tid], v);
    }
    if (tid == 9) {
        unsigned int v = 0u;
#pragma unroll
        for (int w = 0; w < 8; w++) v |= sn[w];
        if (v) atomicAdd(&g_acc[9], 1.0f);
    }

    // ---- last-block finalize (fence -> counter -> compute -> reset) ----
    __threadfence();           // publish this block's atomics GPU-wide
    __syncthreads();           // order all block threads before the arrive
    if (tid == 0) {
        unsigned int old = atomicAdd(&g_count, 1u);
        is_last = (old == (unsigned int)(gridDim.x - 1));
    }
    __syncthreads();
    if (is_last && tid == 0) {
        __threadfence();       // acquire side
        volatile float* ga = g_acc;
        float coord   = LAMBDA_COORD * ga[0];
        float conf    = ga[1];
        float n_noobj = ga[3];
        float noobj1  = ga[2] / fmaxf(n_noobj, 1.0f);
        float noobj2  = ga[4] / (float)ncells;
        if (n_noobj > 0.0f) conf += LAMBDA_NOOBJ * (noobj1 + noobj2);
        float n1 = ga[5], n2 = ga[6];
        float cls_loss = 0.0f;
        if (n1 > 0.0f) cls_loss += ga[7] / fmaxf(n1 * (float)NCLS, 1.0f);
        if (n2 > 0.0f) cls_loss += ga[8] / fmaxf(n2 * (float)NCLS, 1.0f);
        float B = (float)ncells / (float)(SGRID * SGRID);
        float total = (coord + conf + cls_loss) / B;
        out[0] = (ga[9] != 0.0f) ? 0.0f : total;

        // reset global state so the next graph replay starts clean
#pragma unroll
        for (int i = 0; i < 10; i++) g_acc[i] = 0.0f;
        g_count = 0u;
    }
}

extern "C" void kernel_launch(void* const* d_in, const int* in_sizes, int n_in,
                              void* d_out, int out_size) {
    const float* pred = (const float*)d_in[0];
    const float* targ = (const float*)d_in[1];
    float* out = (float*)d_out;

    int total_elems = in_sizes[0];
    int ncells = total_elems / STRIDE;

    yolo_fused_kernel<<<NBLOCKS, 256>>>(pred, targ, out, ncells);
}